// round 4
// baseline (speedup 1.0000x reference)
#include <cuda_runtime.h>
#include <cuda_fp16.h>
#include <math.h>

#define BB 4
#define CC 3
#define HH 384
#define WW 384
#define HWSZ (HH * WW)
#define CHW (CC * HWSZ)

#define INV2SC 50.0f            // 1/(2*0.1^2)
#define INV2SS (1.0f / 98.0f)   // 1/(2*7^2)
#define EPS_LP 1e-6f
#define LOG2E 1.4426950408889634f

// packed-half exp2: 2 exponentials per MUFU op
__device__ __forceinline__ __half2 h2exp2_(__half2 x) {
    unsigned xi = *reinterpret_cast<unsigned*>(&x);
    unsigned ri;
    asm("ex2.approx.f16x2 %0, %1;" : "=r"(ri) : "r"(xi));
    return *reinterpret_cast<__half2*>(&ri);
}

__device__ __forceinline__ float exp2_f(float x) {
    float r;
    asm("ex2.approx.f32 %0, %1;" : "=f"(r) : "f"(x));
    return r;
}

// fp32 lp for the rare border terms
__device__ __forceinline__ float lp_term(float d) {
    return __powf(fmaf(d, d, EPS_LP), 0.4f);
}

__global__ __launch_bounds__(256)
void pair_kernel(const float* __restrict__ inp,
                 const float* __restrict__ tgt,
                 float* __restrict__ out) {
    const int x = blockIdx.x * 32 + threadIdx.x;
    const int y = blockIdx.y * 8 + threadIdx.y;
    const int b = blockIdx.z;
    const int pidx = y * WW + x;

    const float* pi = inp + b * CHW + pidx;
    const float* pt = tgt + b * CHW + pidx;

    const float i0 = pi[0], i1 = pi[HWSZ], i2 = pi[2 * HWSZ];
    const float t0 = pt[0], t1 = pt[HWSZ], t2 = pt[2 * HWSZ];

    // spatial weights exp(-k^2/98), k=0..3 (3 MUFU per thread, negligible)
    float wk[4];
    wk[0] = 1.0f;
    wk[1] = __expf(-1.0f * INV2SS);
    wk[2] = __expf(-4.0f * INV2SS);
    wk[3] = __expf(-9.0f * INV2SS);

    float pacc = 0.0f;

    // 24-offset half-set, in-bounds neighbors, each term counted twice
#pragma unroll
    for (int dy = 0; dy <= 3; dy++) {
        const bool vy = (y + dy) < HH;
#pragma unroll
        for (int dx = -3; dx <= 3; dx++) {
            if (dy == 0 && dx <= 0) continue;           // compile-time
            const bool v = vy && ((unsigned)(x + dx) < (unsigned)WW);
            if (v) {
                const int q = dy * WW + dx;             // immediate
                const float iq0 = __ldg(pi + q);
                const float iq1 = __ldg(pi + q + HWSZ);
                const float iq2 = __ldg(pi + q + 2 * HWSZ);
                const float tq0 = __ldg(pt + q);
                const float tq1 = __ldg(pt + q + HWSZ);
                const float tq2 = __ldg(pt + q + 2 * HWSZ);

                const float d0 = i0 - iq0, d1 = i1 - iq1, d2 = i2 - iq2;
                const float e0 = t0 - tq0, e1 = t1 - tq1, e2 = t2 - tq2;
                const float a0 = fabsf(d0) - fabsf(e0);
                const float a1 = fabsf(d1) - fabsf(e1);
                const float a2 = fabsf(d2) - fabsf(e2);

                const float cd = fmaf(e0, e0, fmaf(e1, e1, e2 * e2));
                const int adx = dx < 0 ? -dx : dx;
                const float ws = wk[dy] * wk[adx];
                // ws*wc = exp2(-(cd*50 + s/98)*log2e), constants folded
                const float sc = -(float)(dy * dy + dx * dx) * INV2SS * LOG2E;
                const float wcs = exp2_f(fmaf(cd, -INV2SC * LOG2E, sc));

                // lp terms: 0.4*log2(t) in fp32, exp2 packed in f16x2
                const float vs0 = 0.4f * __log2f(fmaf(d0, d0, EPS_LP));
                const float vs1 = 0.4f * __log2f(fmaf(d1, d1, EPS_LP));
                const float vs2 = 0.4f * __log2f(fmaf(d2, d2, EPS_LP));
                const float ve0 = 0.4f * __log2f(fmaf(a0, a0, EPS_LP));
                const float ve1 = 0.4f * __log2f(fmaf(a1, a1, EPS_LP));
                const float ve2 = 0.4f * __log2f(fmaf(a2, a2, EPS_LP));

                const __half2 r0 = h2exp2_(__floats2half2_rn(vs0, ve0));
                const __half2 r1 = h2exp2_(__floats2half2_rn(vs1, ve1));
                const __half2 r2 = h2exp2_(__floats2half2_rn(vs2, ve2));
                const __half2 rs = __hadd2(__hadd2(r0, r1), r2);

                const float sm = __low2float(rs);   // lp(d0)+lp(d1)+lp(d2)
                const float ed = __high2float(rs);  // lp(a0)+lp(a1)+lp(a2)

                pacc = fmaf(wcs, sm, pacc);
                pacc = fmaf(ws - wcs, ed, pacc);
            }
        }
    }

    // border: unpaired clamped terms (weight 1), only for edge-band pixels
    float bacc = 0.0f;
    if (x < 3 || x >= WW - 3 || y < 3 || y >= HH - 3) {
#pragma unroll 1
        for (int dy = -3; dy <= 3; dy++) {
#pragma unroll 1
            for (int dx = -3; dx <= 3; dx++) {
                int qx = x + dx, qy = y + dy;
                const bool oob = ((unsigned)qx >= (unsigned)WW) ||
                                 ((unsigned)qy >= (unsigned)HH);
                if (!oob) continue;                 // includes (0,0)
                qx = qx < 0 ? 0 : (qx >= WW ? WW - 1 : qx);
                qy = qy < 0 ? 0 : (qy >= HH ? HH - 1 : qy);
                const int q = (qy - y) * WW + (qx - x);

                const float iq0 = __ldg(pi + q);
                const float iq1 = __ldg(pi + q + HWSZ);
                const float iq2 = __ldg(pi + q + 2 * HWSZ);
                const float tq0 = __ldg(pt + q);
                const float tq1 = __ldg(pt + q + HWSZ);
                const float tq2 = __ldg(pt + q + 2 * HWSZ);

                const float d0 = i0 - iq0, d1 = i1 - iq1, d2 = i2 - iq2;
                const float e0 = t0 - tq0, e1 = t1 - tq1, e2 = t2 - tq2;

                const float cd = fmaf(e0, e0, fmaf(e1, e1, e2 * e2));
                const float sdist = (float)(dy * dy + dx * dx);
                const float ws = __expf(-sdist * INV2SS);
                const float wcs = __expf(-fmaf(cd, INV2SC, sdist * INV2SS));

                const float sm = lp_term(d0) + lp_term(d1) + lp_term(d2);
                const float ed = lp_term(fabsf(d0) - fabsf(e0))
                               + lp_term(fabsf(d1) - fabsf(e1))
                               + lp_term(fabsf(d2) - fabsf(e2));

                bacc = fmaf(wcs, sm, bacc);
                bacc = fmaf(ws - wcs, ed, bacc);
            }
        }
    }

    const float l2 = (i0 - t0) * (i0 - t0)
                   + (i1 - t1) * (i1 - t1)
                   + (i2 - t2) * (i2 - t2);
    float acc = fmaf(2.0f, pacc, l2 + bacc);

    // ---- reduction: warp shuffle -> block -> one atomic ----
    const unsigned FULL = 0xFFFFFFFFu;
#pragma unroll
    for (int off = 16; off > 0; off >>= 1)
        acc += __shfl_down_sync(FULL, acc, off);

    __shared__ float wsum[8];
    const int tid = threadIdx.y * 32 + threadIdx.x;
    const int wid = tid >> 5, lid = tid & 31;
    if (lid == 0) wsum[wid] = acc;
    __syncthreads();
    if (wid == 0) {
        float v = (lid < 8) ? wsum[lid] : 0.0f;
#pragma unroll
        for (int off = 4; off > 0; off >>= 1)
            v += __shfl_down_sync(FULL, v, off);
        if (lid == 0) {
            const float inv_n = 1.0f / (float)(BB * CC * HH * WW);
            atomicAdd(out, v * inv_n);
        }
    }
}

extern "C" void kernel_launch(void* const* d_in, const int* in_sizes, int n_in,
                              void* d_out, int out_size) {
    (void)in_sizes; (void)n_in;
    const float* inp = (const float*)d_in[0];
    const float* tgt = (const float*)d_in[1];
    float* out = (float*)d_out;

    if (out_size >= 1) cudaMemsetAsync(out, 0, sizeof(float));

    dim3 block(32, 8, 1);
    dim3 grid(WW / 32, HH / 8, BB);
    pair_kernel<<<grid, block>>>(inp, tgt, out);
}